// round 8
// baseline (speedup 1.0000x reference)
#include <cuda_runtime.h>
#include <math.h>
#include <stdint.h>

// Problem constants (fixed by the reference)
#define NW      65536
#define TPB     128
#define PPB     256                // walker pairs per block (2 chains/thread)
#define NBLK    128                // 32768 pairs / 256; divides 2^32
#define TOTALS  512
#define WARM    128
#define NSTEPS  384
#define CH      8                  // steps per chunk
#define HB      4                  // steps per precompute half-block
#define NCH     (TOTALS / CH)      // 64
#define WARM_CH (WARM / CH)        // 16
#define ROWB    ((size_t)NW * 4)   // gmem bytes per step-row
// smem ring (ull units): stage = [N: CH*PPB][U: CH*PPB]
#define UOFF    (CH * PPB)         // 2048 ull
#define STG     (2 * CH * PPB)     // 4096 ull = 32 KB
#define SMEM_BYTES (4 * STG * 8)   // 128 KB

typedef unsigned long long ull;

__device__ float        g_part[8][NBLK];
__device__ unsigned int g_ctr = 0;

// ---------- f32x2 packed helpers ----------
__device__ __forceinline__ ull PKF(float a, float b) {
    ull v; asm("mov.b64 %0, {%1, %2};" : "=l"(v)
               : "r"(__float_as_uint(a)), "r"(__float_as_uint(b)));
    return v;
}
__device__ __forceinline__ ull PKU(unsigned a, unsigned b) {
    ull v; asm("mov.b64 %0, {%1, %2};" : "=l"(v) : "r"(a), "r"(b));
    return v;
}
__device__ __forceinline__ float LO(ull v) { return __uint_as_float((unsigned)v); }
__device__ __forceinline__ float HI(ull v) { return __uint_as_float((unsigned)(v >> 32)); }
__device__ __forceinline__ ull FMA2(ull a, ull b, ull c) {
    ull d; asm("fma.rn.f32x2 %0, %1, %2, %3;" : "=l"(d) : "l"(a), "l"(b), "l"(c));
    return d;
}
__device__ __forceinline__ ull MUL2(ull a, ull b) {
    ull d; asm("mul.rn.f32x2 %0, %1, %2;" : "=l"(d) : "l"(a), "l"(b));
    return d;
}
__device__ __forceinline__ ull ADD2(ull a, ull b) {
    ull d; asm("add.rn.f32x2 %0, %1, %2;" : "=l"(d) : "l"(a), "l"(b));
    return d;
}
__device__ __forceinline__ ull SPL(float a) { return PKF(a, a); }

__device__ __forceinline__ void cp16(uint32_t dst, const void* src) {
    asm volatile("cp.async.cg.shared.global [%0], [%1], 16;" :: "r"(dst), "l"(src));
}

__global__ void __launch_bounds__(TPB) vmc_kernel(
    const float* __restrict__ theta,
    const float* __restrict__ r0,
    const float* __restrict__ sdevp,
    const float* __restrict__ noise,
    const float* __restrict__ unif,
    float* __restrict__ out, int out_size)
{
    extern __shared__ ull ring[];
    float* shred = (float*)ring;             // aliased reduction scratch

    const int tid = threadIdx.x;
    const int blk = blockIdx.x;

    const float th0 = theta[0];
    const float th1 = theta[1];
    const float th2 = theta[2];
    const float sdev = sdevp[0];

    const float kk = __fmul_rn(-2.0f, th1);   // reference rounding (validated)
    const float gf = 2.0f * th1;

    const ull sd2  = SPL(sdev);
    const ull kk2  = SPL(kk);
    const ull mkk2 = SPL(-kk);

    // njuffa natural-log poly constants (validated in R3: rel_err == logf path)
    const ull cm1 = SPL(-1.0f);
    const ull cLA = SPL(-0.130310059f), cLB = SPL(-0.121483512f);
    const ull cLC = SPL( 0.140869141f), cLD = SPL( 0.139814854f);
    const ull cLE = SPL(-0.166846126f), cLF = SPL( 0.200120345f);
    const ull cLG = SPL(-0.249996200f), cLH = SPL( 0.333331972f);
    const ull cLI = SPL(-0.5f),         cLN2 = SPL(0.693147182f);

    // Energy polys in t = xs^2, coeffs folded in fp64 once
    const double dth0 = (double)th0, dth1 = (double)th1;
    const double dg = 2.0 * dth1, g2d = dg * dg;
    const double dC1 = -2.0 * exp(-dth1) * cos(dth0);
    const double dC2 =  2.0 * exp(-dth1) * sin(dth0);
    const ull A0 = SPL((float)dC1);
    const ull A1 = SPL((float)(dC1 * g2d / 2.0));
    const ull A2 = SPL((float)(dC1 * g2d * g2d / 24.0));
    const ull A3 = SPL((float)(dC1 * g2d * g2d * g2d / 720.0));
    const ull B0 = SPL((float)(dC2 * dg));
    const ull B1 = SPL((float)(dC2 * dg * g2d / 6.0));
    const ull B2 = SPL((float)(dC2 * dg * g2d * g2d / 120.0));

    // ---- two independent chains: pairs A = blk*256+tid, B = +128 ----
    const float2 rA = ((const float2*)r0)[blk * PPB + tid];
    const float2 rB = ((const float2*)r0)[blk * PPB + 128 + tid];
    ull xsA  = PKF(__fsub_rn(rA.x, th2), __fsub_rn(rA.y, th2));
    ull xsB  = PKF(__fsub_rn(rB.x, th2), __fsub_rn(rB.y, th2));
    ull xs2A = MUL2(xsA, xsA), xs2B = MUL2(xsB, xsB);
    ull nkxA = MUL2(mkk2, xs2A), nkxB = MUL2(mkk2, xs2B);

    // ---- cp.async geometry: row = 256 pairs = 2048 B = 128 granules ----
    const uint32_t base = (uint32_t)__cvta_generic_to_shared(ring);
    const size_t sliceOff = (size_t)blk * 2048 + (size_t)tid * 16;
    const char* gN = (const char*)noise + sliceOff;
    const char* gU = (const char*)unif  + sliceOff;

#define ISSUE_CHUNK(s0, stg) do {                                            \
        const char* _n = gN + (size_t)(s0) * ROWB;                           \
        const char* _u = gU + (size_t)(s0) * ROWB;                           \
        uint32_t _sb = base + (uint32_t)(stg) * (STG * 8);                   \
        _Pragma("unroll")                                                    \
        for (int _r = 0; _r < CH; _r++) {                                    \
            uint32_t _d = (uint32_t)(_r * 2048 + tid * 16);                  \
            cp16(_sb + _d,            _n + (size_t)_r * ROWB);               \
            cp16(_sb + UOFF * 8 + _d, _u + (size_t)_r * ROWB);               \
        }                                                                    \
        asm volatile("cp.async.commit_group;" ::: "memory");                 \
    } while (0)

    // packed natural log (off-chain, data-parallel); validated R3
#define NLOG(u, lgu) do {                                                    \
        unsigned iu0 = (unsigned)(u);                                        \
        unsigned iu1 = (unsigned)((u) >> 32);                                \
        int e0 = (int)((iu0 - 0x3f2aaaabu) & 0xff800000u);                   \
        int e1 = (int)((iu1 - 0x3f2aaaabu) & 0xff800000u);                   \
        float mm0 = __int_as_float((int)iu0 - e0);                           \
        float mm1 = __int_as_float((int)iu1 - e1);                           \
        float ie0 = (float)e0 * 1.19209290e-7f;                              \
        float ie1 = (float)e1 * 1.19209290e-7f;                              \
        ull f_ = ADD2(PKF(mm0, mm1), cm1);                                   \
        ull s_ = MUL2(f_, f_);                                               \
        ull r_ = FMA2(cLA, s_, cLB);                                         \
        ull t_ = FMA2(cLC, s_, cLD);                                         \
        r_ = FMA2(r_, s_, cLE);                                              \
        t_ = FMA2(t_, s_, cLF);                                              \
        r_ = FMA2(r_, s_, cLG);                                              \
        r_ = FMA2(t_, f_, r_);                                               \
        r_ = FMA2(r_, f_, cLH);                                              \
        r_ = FMA2(r_, f_, cLI);                                              \
        r_ = FMA2(r_, s_, f_);                                               \
        (lgu) = FMA2(PKF(ie0, ie1), cLN2, r_);                               \
    } while (0)

    // short recurrence: only xp, xp2, lr, compare, select on the chain
#define REC(sn, lg, XS, XS2, NKX) do {                                       \
        ull xp  = ADD2(XS, (sn));                                            \
        ull xp2 = MUL2(xp, xp);                                              \
        ull lr  = FMA2(kk2, xp2, NKX);                                       \
        bool aLo = (LO(lg) < LO(lr));                                        \
        bool aHi = (HI(lg) < HI(lr));                                        \
        unsigned xs_lo = aLo ? (unsigned)xp         : (unsigned)XS;          \
        unsigned xs_hi = aHi ? (unsigned)(xp  >> 32) : (unsigned)(XS  >> 32); \
        unsigned x2_lo = aLo ? (unsigned)xp2        : (unsigned)XS2;         \
        unsigned x2_hi = aHi ? (unsigned)(xp2 >> 32) : (unsigned)(XS2 >> 32); \
        XS  = PKU(xs_lo, xs_hi);                                             \
        XS2 = PKU(x2_lo, x2_hi);                                             \
        NKX = MUL2(mkk2, XS2);                                               \
    } while (0)

#define MEAS(XS, XS2) do {                                                   \
        ull t  = XS2;                                                        \
        ull er = FMA2(A3, t, A2);                                            \
        er = FMA2(er, t, A1); er = FMA2(er, t, A0);                          \
        ull pb = FMA2(B2, t, B1);                                            \
        pb = FMA2(pb, t, B0);                                                \
        ull ei = MUL2(XS, pb);                                               \
        S0 = ADD2(S0, er);                                                   \
        S1 = ADD2(S1, ei);                                                   \
        S2 = ADD2(S2, XS);                                                   \
        S3 = ADD2(S3, t);                                                    \
        S4 = FMA2(XS, er, S4);                                               \
        S5 = FMA2(XS, ei, S5);                                               \
        S6 = FMA2(t,  er, S6);                                               \
        S7 = FMA2(t,  ei, S7);                                               \
    } while (0)

    ull S0 = 0, S1 = 0, S2 = 0, S3 = 0, S4 = 0, S5 = 0, S6 = 0, S7 = 0;

    ISSUE_CHUNK(0 * CH, 0);
    ISSUE_CHUNK(1 * CH, 1);
    ISSUE_CHUNK(2 * CH, 2);

    for (int c = 0; c < NCH; c++) {
        asm volatile("cp.async.wait_group 2;" ::: "memory");
        __syncthreads();

        if (c + 3 < NCH) {
            ISSUE_CHUNK((c + 3) * CH, (c + 3) & 3);
        } else {
            asm volatile("cp.async.commit_group;" ::: "memory");
        }

        const ull* st = ring + (size_t)(c & 3) * STG;
        const bool meas = (c >= WARM_CH);

        // process chunk in two half-blocks of HB=4 steps to cap live regs
#pragma unroll
        for (int h = 0; h < CH / HB; h++) {
            // --- chunk-front precompute: sn = sd*n, lg = log(u); off-chain ---
            ull snA[HB], lgA[HB], snB[HB], lgB[HB];
#pragma unroll
            for (int j = 0; j < HB; j++) {
                const int row = h * HB + j;
                ull nA = st[row * PPB + tid];
                ull uA = st[UOFF + row * PPB + tid];
                ull nB = st[row * PPB + 128 + tid];
                ull uB = st[UOFF + row * PPB + 128 + tid];
                snA[j] = MUL2(sd2, nA);
                snB[j] = MUL2(sd2, nB);
                NLOG(uA, lgA[j]);
                NLOG(uB, lgB[j]);
            }
            // --- short-chain recurrence ---
            if (!meas) {
#pragma unroll
                for (int j = 0; j < HB; j++) {
                    REC(snA[j], lgA[j], xsA, xs2A, nkxA);
                    REC(snB[j], lgB[j], xsB, xs2B, nkxB);
                }
            } else {
#pragma unroll
                for (int j = 0; j < HB; j++) {
                    REC(snA[j], lgA[j], xsA, xs2A, nkxA);
                    REC(snB[j], lgB[j], xsB, xs2B, nkxB);
                    MEAS(xsA, xs2A);
                    MEAS(xsB, xs2B);
                }
            }
        }
    }

    // ---------------- block reduction (4 warps) ----------------
    float v0 = LO(S0) + HI(S0), v1 = LO(S1) + HI(S1);
    float v2 = LO(S2) + HI(S2), v3 = LO(S3) + HI(S3);
    float v4 = LO(S4) + HI(S4), v5 = LO(S5) + HI(S5);
    float v6 = LO(S6) + HI(S6), v7 = LO(S7) + HI(S7);

    const unsigned m = 0xffffffffu;
#pragma unroll
    for (int o = 16; o; o >>= 1) {
        v0 += __shfl_xor_sync(m, v0, o);
        v1 += __shfl_xor_sync(m, v1, o);
        v2 += __shfl_xor_sync(m, v2, o);
        v3 += __shfl_xor_sync(m, v3, o);
        v4 += __shfl_xor_sync(m, v4, o);
        v5 += __shfl_xor_sync(m, v5, o);
        v6 += __shfl_xor_sync(m, v6, o);
        v7 += __shfl_xor_sync(m, v7, o);
    }

    float* sh   = shred;            // [8][4]
    float* s8   = shred + 32;       // [8]
    int*  sLast = (int*)(shred + 40);

    __syncthreads();                // ring reads done before aliasing
    const int lane = tid & 31;
    const int wp   = tid >> 5;      // 4 warps
    if (lane == 0) {
        sh[0 * 4 + wp] = v0; sh[1 * 4 + wp] = v1;
        sh[2 * 4 + wp] = v2; sh[3 * 4 + wp] = v3;
        sh[4 * 4 + wp] = v4; sh[5 * 4 + wp] = v5;
        sh[6 * 4 + wp] = v6; sh[7 * 4 + wp] = v7;
    }
    __syncthreads();
    if (tid < 32) {
        const int q  = tid >> 2;
        const int wj = tid & 3;
        float v = sh[q * 4 + wj];
        v += __shfl_down_sync(m, v, 2, 4);
        v += __shfl_down_sync(m, v, 1, 4);
        if (wj == 0) g_part[q][blk] = v;
    }
    __threadfence();
    __syncthreads();
    if (tid == 0) {
        unsigned old = atomicAdd(&g_ctr, 1u);
        *sLast = ((old % NBLK) == (NBLK - 1)) ? 1 : 0;
    }
    __syncthreads();

    // ---------------- last block: final reduce + output ----------------
    if (*sLast) {
        const int q = tid >> 4;     // 8 quantities x 16 lanes
        const int l = tid & 15;
        float v = 0.f;
#pragma unroll
        for (int i = l; i < NBLK; i += 16) v += __ldcg(&g_part[q][i]);
#pragma unroll
        for (int o = 8; o; o >>= 1) v += __shfl_down_sync(m, v, o, 16);
        if (l == 0) s8[q] = v;
        __syncthreads();

        if (tid == 0) {
            const float inv = 1.0f / ((float)NW * (float)NSTEPS);
            const float Ser   = s8[0] * inv;
            const float Sei   = s8[1] * inv;
            const float Sxs   = s8[2] * inv;   // mean(r) - th2
            const float Sx2   = s8[3] * inv;
            const float Sxer  = s8[4] * inv;
            const float Sxei  = s8[5] * inv;
            const float Sx2er = s8[6] * inv;
            const float Sx2ei = s8[7] * inv;

            if (out_size == 14) {
                const float Sr   = Sxs + th2;
                const float Srer = Sxer + th2 * Ser;
                const float Srei = Sxei + th2 * Sei;
                float2* o2 = (float2*)out;
                o2[0] = make_float2(Ser, Sei);
                o2[1] = make_float2(0.0f, Sr);
                o2[2] = make_float2(Sx2, 0.0f);
                o2[3] = make_float2(gf * Sxs, 0.0f);
                o2[4] = make_float2(Srei, -Srer);
                o2[5] = make_float2(Sx2er, Sx2ei);
                o2[6] = make_float2(gf * Sxer, gf * Sxei);
            } else {
                out[0] = Ser;                  // Es.re
                out[1] = 0.0f;                 // Ds0.re
                out[2] = Sx2;                  // Ds1.re
                out[3] = gf * Sxs;             // Ds2.re
                out[4] = Sxei + th2 * Sei;     // EDs0.re
                out[5] = Sx2er;                // EDs1.re
                out[6] = gf * Sxer;            // EDs2.re
            }
        }
    }
}

extern "C" void kernel_launch(void* const* d_in, const int* in_sizes, int n_in,
                              void* d_out, int out_size)
{
    const float* theta = (const float*)d_in[0];
    const float* r0    = (const float*)d_in[1];
    const float* sdev  = (const float*)d_in[2];
    const float* noise = (const float*)d_in[3];
    const float* unif  = (const float*)d_in[4];

    cudaFuncSetAttribute(vmc_kernel, cudaFuncAttributeMaxDynamicSharedMemorySize,
                         SMEM_BYTES);

    vmc_kernel<<<NBLK, TPB, SMEM_BYTES>>>(theta, r0, sdev, noise, unif,
                                          (float*)d_out, out_size);
}

// round 9
// speedup vs baseline: 1.0594x; 1.0594x over previous
#include <cuda_runtime.h>
#include <math.h>
#include <stdint.h>

// Problem constants (fixed by the reference)
#define NW      65536
#define TPB     256
#define PPB     256                // walker pairs per block (1 packed pair/thread)
#define NBLK    128                // 32768 pairs / 256; divides 2^32
#define TOTALS  512
#define WARM    128
#define NSTEPS  384
#define CH      8                  // steps per chunk
#define HB      4                  // steps per precompute half-block
#define NCH     (TOTALS / CH)      // 64
#define WARM_CH (WARM / CH)        // 16
#define ROWB    ((size_t)NW * 4)   // gmem bytes per step-row
// smem ring (ull units): stage = [N: CH*PPB][U: CH*PPB]
#define UOFF    (CH * PPB)         // 2048 ull
#define STG     (2 * CH * PPB)     // 4096 ull = 32 KB
#define SMEM_BYTES (4 * STG * 8)   // 128 KB

typedef unsigned long long ull;

__device__ float        g_part[8][NBLK];
__device__ unsigned int g_ctr = 0;

// ---------- f32x2 packed helpers ----------
__device__ __forceinline__ ull PKF(float a, float b) {
    ull v; asm("mov.b64 %0, {%1, %2};" : "=l"(v)
               : "r"(__float_as_uint(a)), "r"(__float_as_uint(b)));
    return v;
}
__device__ __forceinline__ ull PKU(unsigned a, unsigned b) {
    ull v; asm("mov.b64 %0, {%1, %2};" : "=l"(v) : "r"(a), "r"(b));
    return v;
}
__device__ __forceinline__ float LO(ull v) { return __uint_as_float((unsigned)v); }
__device__ __forceinline__ float HI(ull v) { return __uint_as_float((unsigned)(v >> 32)); }
__device__ __forceinline__ ull FMA2(ull a, ull b, ull c) {
    ull d; asm("fma.rn.f32x2 %0, %1, %2, %3;" : "=l"(d) : "l"(a), "l"(b), "l"(c));
    return d;
}
__device__ __forceinline__ ull MUL2(ull a, ull b) {
    ull d; asm("mul.rn.f32x2 %0, %1, %2;" : "=l"(d) : "l"(a), "l"(b));
    return d;
}
__device__ __forceinline__ ull ADD2(ull a, ull b) {
    ull d; asm("add.rn.f32x2 %0, %1, %2;" : "=l"(d) : "l"(a), "l"(b));
    return d;
}
__device__ __forceinline__ ull SPL(float a) { return PKF(a, a); }

__device__ __forceinline__ void cp16(uint32_t dst, const void* src) {
    asm volatile("cp.async.cg.shared.global [%0], [%1], 16;" :: "r"(dst), "l"(src));
}

__global__ void __launch_bounds__(TPB, 1) vmc_kernel(
    const float* __restrict__ theta,
    const float* __restrict__ r0,
    const float* __restrict__ sdevp,
    const float* __restrict__ noise,
    const float* __restrict__ unif,
    float* __restrict__ out, int out_size)
{
    extern __shared__ ull ring[];
    float* shred = (float*)ring;             // aliased reduction scratch

    const int tid = threadIdx.x;
    const int blk = blockIdx.x;
    const int w   = blk * PPB + tid;         // walker-pair index

    const float th0 = theta[0];
    const float th1 = theta[1];
    const float th2 = theta[2];
    const float sdev = sdevp[0];

    const float kk = __fmul_rn(-2.0f, th1);   // reference rounding (validated)
    const float gf = 2.0f * th1;

    const ull sd2  = SPL(sdev);
    const ull kk2  = SPL(kk);
    const ull mkk2 = SPL(-kk);

    // njuffa natural-log poly constants (validated R3: matches logf accepts)
    const ull cm1 = SPL(-1.0f);
    const ull cLA = SPL(-0.130310059f), cLB = SPL(-0.121483512f);
    const ull cLC = SPL( 0.140869141f), cLD = SPL( 0.139814854f);
    const ull cLE = SPL(-0.166846126f), cLF = SPL( 0.200120345f);
    const ull cLG = SPL(-0.249996200f), cLH = SPL( 0.333331972f);
    const ull cLI = SPL(-0.5f),         cLN2 = SPL(0.693147182f);

    // Energy polys in t = xs^2, coeffs folded in fp64 once
    const double dth0 = (double)th0, dth1 = (double)th1;
    const double dg = 2.0 * dth1, g2d = dg * dg;
    const double dC1 = -2.0 * exp(-dth1) * cos(dth0);
    const double dC2 =  2.0 * exp(-dth1) * sin(dth0);
    const ull A0 = SPL((float)dC1);
    const ull A1 = SPL((float)(dC1 * g2d / 2.0));
    const ull A2 = SPL((float)(dC1 * g2d / 2.0 * g2d / 12.0));
    const ull A3 = SPL((float)(dC1 * g2d / 2.0 * g2d / 12.0 * g2d / 30.0));
    const ull B0 = SPL((float)(dC2 * dg));
    const ull B1 = SPL((float)(dC2 * dg * g2d / 6.0));
    const ull B2 = SPL((float)(dC2 * dg * g2d / 6.0 * g2d / 20.0));

    // ---- state: one packed pair per thread ----
    const float2 rr = ((const float2*)r0)[w];
    ull xs  = PKF(__fsub_rn(rr.x, th2), __fsub_rn(rr.y, th2));
    ull xs2 = MUL2(xs, xs);
    ull nkx = MUL2(mkk2, xs2);

    // ---- cp.async geometry (R5-validated): row = 2048 B = 128 granules ----
    const uint32_t base = (uint32_t)__cvta_generic_to_shared(ring);
    const int c16  = tid & 127;               // granule within row
    const int rsel = tid >> 7;                // 0/1 -> rows rsel+{0,2,4,6}
    const size_t sliceOff = (size_t)blk * 2048 + (size_t)c16 * 16;
    const char* gN = (const char*)noise + sliceOff;
    const char* gU = (const char*)unif  + sliceOff;

#define ISSUE_CHUNK(s0, stg) do {                                            \
        const char* _n = gN + (size_t)(s0) * ROWB;                           \
        const char* _u = gU + (size_t)(s0) * ROWB;                           \
        uint32_t _sb = base + (uint32_t)(stg) * (STG * 8);                   \
        _Pragma("unroll")                                                    \
        for (int _k = 0; _k < 4; _k++) {                                     \
            int _row = _k * 2 + rsel;                                        \
            uint32_t _d = (uint32_t)(_row * 2048 + c16 * 16);                \
            cp16(_sb + _d,            _n + (size_t)_row * ROWB);             \
            cp16(_sb + UOFF * 8 + _d, _u + (size_t)_row * ROWB);             \
        }                                                                    \
        asm volatile("cp.async.commit_group;" ::: "memory");                 \
    } while (0)

    // packed natural log (off-chain, data-parallel)
#define NLOG(u, lgu) do {                                                    \
        unsigned iu0 = (unsigned)(u);                                        \
        unsigned iu1 = (unsigned)((u) >> 32);                                \
        int e0 = (int)((iu0 - 0x3f2aaaabu) & 0xff800000u);                   \
        int e1 = (int)((iu1 - 0x3f2aaaabu) & 0xff800000u);                   \
        float mm0 = __int_as_float((int)iu0 - e0);                           \
        float mm1 = __int_as_float((int)iu1 - e1);                           \
        float ie0 = (float)e0 * 1.19209290e-7f;                              \
        float ie1 = (float)e1 * 1.19209290e-7f;                              \
        ull f_ = ADD2(PKF(mm0, mm1), cm1);                                   \
        ull s_ = MUL2(f_, f_);                                               \
        ull r_ = FMA2(cLA, s_, cLB);                                         \
        ull t_ = FMA2(cLC, s_, cLD);                                         \
        r_ = FMA2(r_, s_, cLE);                                              \
        t_ = FMA2(t_, s_, cLF);                                              \
        r_ = FMA2(r_, s_, cLG);                                              \
        r_ = FMA2(t_, f_, r_);                                               \
        r_ = FMA2(r_, f_, cLH);                                              \
        r_ = FMA2(r_, f_, cLI);                                              \
        r_ = FMA2(r_, s_, f_);                                               \
        (lgu) = FMA2(PKF(ie0, ie1), cLN2, r_);                               \
    } while (0)

    // short recurrence: add -> mul -> fma -> cmp/sel -> mul; ~24 cyc chain
#define REC(sn, lg) do {                                                     \
        ull xp  = ADD2(xs, (sn));                                            \
        ull xp2 = MUL2(xp, xp);                                              \
        ull lr  = FMA2(kk2, xp2, nkx);                                       \
        bool aLo = (LO(lg) < LO(lr));                                        \
        bool aHi = (HI(lg) < HI(lr));                                        \
        unsigned xs_lo = aLo ? (unsigned)xp         : (unsigned)xs;          \
        unsigned xs_hi = aHi ? (unsigned)(xp  >> 32) : (unsigned)(xs  >> 32); \
        unsigned x2_lo = aLo ? (unsigned)xp2        : (unsigned)xs2;         \
        unsigned x2_hi = aHi ? (unsigned)(xp2 >> 32) : (unsigned)(xs2 >> 32); \
        xs  = PKU(xs_lo, xs_hi);                                             \
        xs2 = PKU(x2_lo, x2_hi);                                             \
        nkx = MUL2(mkk2, xs2);                                               \
    } while (0)

#define MEAS() do {                                                          \
        ull t  = xs2;                                                        \
        ull er = FMA2(A3, t, A2);                                            \
        er = FMA2(er, t, A1); er = FMA2(er, t, A0);                          \
        ull pb = FMA2(B2, t, B1);                                            \
        pb = FMA2(pb, t, B0);                                                \
        ull ei = MUL2(xs, pb);                                               \
        S0 = ADD2(S0, er);                                                   \
        S1 = ADD2(S1, ei);                                                   \
        S2 = ADD2(S2, xs);                                                   \
        S3 = ADD2(S3, t);                                                    \
        S4 = FMA2(xs, er, S4);                                               \
        S5 = FMA2(xs, ei, S5);                                               \
        S6 = FMA2(t,  er, S6);                                               \
        S7 = FMA2(t,  ei, S7);                                               \
    } while (0)

    ull S0 = 0, S1 = 0, S2 = 0, S3 = 0, S4 = 0, S5 = 0, S6 = 0, S7 = 0;

    ISSUE_CHUNK(0 * CH, 0);
    ISSUE_CHUNK(1 * CH, 1);
    ISSUE_CHUNK(2 * CH, 2);

    for (int c = 0; c < NCH; c++) {
        asm volatile("cp.async.wait_group 2;" ::: "memory");
        __syncthreads();

        if (c + 3 < NCH) {
            ISSUE_CHUNK((c + 3) * CH, (c + 3) & 3);
        } else {
            asm volatile("cp.async.commit_group;" ::: "memory");
        }

        const ull* st = ring + (size_t)(c & 3) * STG;
        const bool meas = (c >= WARM_CH);

        // half-blocks of HB=4 steps: precompute sn/log off-chain, then recur
#pragma unroll
        for (int h = 0; h < CH / HB; h++) {
            ull sn[HB], lg[HB];
#pragma unroll
            for (int j = 0; j < HB; j++) {
                const int row = h * HB + j;
                ull n = st[row * PPB + tid];
                ull u = st[UOFF + row * PPB + tid];
                sn[j] = MUL2(sd2, n);
                NLOG(u, lg[j]);
            }
            if (!meas) {
#pragma unroll
                for (int j = 0; j < HB; j++) { REC(sn[j], lg[j]); }
            } else {
#pragma unroll
                for (int j = 0; j < HB; j++) { REC(sn[j], lg[j]); MEAS(); }
            }
        }
    }

    // ---------------- block reduction (8 warps) ----------------
    float v0 = LO(S0) + HI(S0), v1 = LO(S1) + HI(S1);
    float v2 = LO(S2) + HI(S2), v3 = LO(S3) + HI(S3);
    float v4 = LO(S4) + HI(S4), v5 = LO(S5) + HI(S5);
    float v6 = LO(S6) + HI(S6), v7 = LO(S7) + HI(S7);

    const unsigned m = 0xffffffffu;
#pragma unroll
    for (int o = 16; o; o >>= 1) {
        v0 += __shfl_xor_sync(m, v0, o);
        v1 += __shfl_xor_sync(m, v1, o);
        v2 += __shfl_xor_sync(m, v2, o);
        v3 += __shfl_xor_sync(m, v3, o);
        v4 += __shfl_xor_sync(m, v4, o);
        v5 += __shfl_xor_sync(m, v5, o);
        v6 += __shfl_xor_sync(m, v6, o);
        v7 += __shfl_xor_sync(m, v7, o);
    }

    float* sh   = shred;            // [8][8]
    float* s8   = shred + 64;       // [8]
    int*  sLast = (int*)(shred + 72);

    __syncthreads();                // ring reads done before aliasing
    const int lane = tid & 31;
    const int wp   = tid >> 5;      // 8 warps
    if (lane == 0) {
        sh[0 * 8 + wp] = v0; sh[1 * 8 + wp] = v1;
        sh[2 * 8 + wp] = v2; sh[3 * 8 + wp] = v3;
        sh[4 * 8 + wp] = v4; sh[5 * 8 + wp] = v5;
        sh[6 * 8 + wp] = v6; sh[7 * 8 + wp] = v7;
    }
    __syncthreads();
    if (tid < 64) {
        const int q  = tid >> 3;
        const int wj = tid & 7;
        float v = sh[q * 8 + wj];
        v += __shfl_down_sync(m, v, 4, 8);
        v += __shfl_down_sync(m, v, 2, 8);
        v += __shfl_down_sync(m, v, 1, 8);
        if (wj == 0) g_part[q][blk] = v;
    }
    __threadfence();
    __syncthreads();
    if (tid == 0) {
        unsigned old = atomicAdd(&g_ctr, 1u);
        *sLast = ((old % NBLK) == (NBLK - 1)) ? 1 : 0;
    }
    __syncthreads();

    // ---------------- last block: final reduce + output ----------------
    if (*sLast) {
        if (tid < 128) {
            const int q = tid >> 4;   // 8 quantities x 16 lanes
            const int l = tid & 15;
            float v = 0.f;
#pragma unroll
            for (int i = l; i < NBLK; i += 16) v += __ldcg(&g_part[q][i]);
#pragma unroll
            for (int o = 8; o; o >>= 1) v += __shfl_down_sync(m, v, o, 16);
            if (l == 0) s8[q] = v;
        }
        __syncthreads();

        if (tid == 0) {
            const float inv = 1.0f / ((float)NW * (float)NSTEPS);
            const float Ser   = s8[0] * inv;
            const float Sei   = s8[1] * inv;
            const float Sxs   = s8[2] * inv;   // mean(r) - th2
            const float Sx2   = s8[3] * inv;
            const float Sxer  = s8[4] * inv;
            const float Sxei  = s8[5] * inv;
            const float Sx2er = s8[6] * inv;
            const float Sx2ei = s8[7] * inv;

            if (out_size == 14) {
                const float Sr   = Sxs + th2;
                const float Srer = Sxer + th2 * Ser;
                const float Srei = Sxei + th2 * Sei;
                float2* o2 = (float2*)out;
                o2[0] = make_float2(Ser, Sei);
                o2[1] = make_float2(0.0f, Sr);
                o2[2] = make_float2(Sx2, 0.0f);
                o2[3] = make_float2(gf * Sxs, 0.0f);
                o2[4] = make_float2(Srei, -Srer);
                o2[5] = make_float2(Sx2er, Sx2ei);
                o2[6] = make_float2(gf * Sxer, gf * Sxei);
            } else {
                out[0] = Ser;                  // Es.re
                out[1] = 0.0f;                 // Ds0.re
                out[2] = Sx2;                  // Ds1.re
                out[3] = gf * Sxs;             // Ds2.re
                out[4] = Sxei + th2 * Sei;     // EDs0.re
                out[5] = Sx2er;                // EDs1.re
                out[6] = gf * Sxer;            // EDs2.re
            }
        }
    }
}

extern "C" void kernel_launch(void* const* d_in, const int* in_sizes, int n_in,
                              void* d_out, int out_size)
{
    const float* theta = (const float*)d_in[0];
    const float* r0    = (const float*)d_in[1];
    const float* sdev  = (const float*)d_in[2];
    const float* noise = (const float*)d_in[3];
    const float* unif  = (const float*)d_in[4];

    cudaFuncSetAttribute(vmc_kernel, cudaFuncAttributeMaxDynamicSharedMemorySize,
                         SMEM_BYTES);

    vmc_kernel<<<NBLK, TPB, SMEM_BYTES>>>(theta, r0, sdev, noise, unif,
                                          (float*)d_out, out_size);
}

// round 11
// speedup vs baseline: 1.2536x; 1.1833x over previous
#include <cuda_runtime.h>
#include <math.h>
#include <stdint.h>

// Problem constants (fixed by the reference)
#define NW      65536
#define TPB     256
#define PPB     256                // walker pairs per block (1 packed pair/thread)
#define NBLK    128                // 32768 pairs / 256; divides 2^32
#define TOTALS  512
#define WARM    128
#define NSTEPS  384
#define CH      8                  // steps per chunk
#define HB      4                  // steps per precompute half-block
#define NCH     (TOTALS / CH)      // 64
#define WARM_CH (WARM / CH)        // 16
#define ROWB    ((size_t)NW * 4)   // gmem bytes per step-row
// smem ring (ull units): stage = [N: CH*PPB][U: CH*PPB]
#define UOFF    (CH * PPB)         // 2048 ull
#define STG     (2 * CH * PPB)     // 4096 ull = 32 KB
#define SMEM_BYTES (4 * STG * 8)   // 128 KB

typedef unsigned long long ull;

// 8 slots (6 moments + 2 zero pads) to keep the validated R9 reduction shape
__device__ float        g_part[8][NBLK];
__device__ unsigned int g_ctr = 0;

// ---------- f32x2 packed helpers ----------
__device__ __forceinline__ ull PKF(float a, float b) {
    ull v; asm("mov.b64 %0, {%1, %2};" : "=l"(v)
               : "r"(__float_as_uint(a)), "r"(__float_as_uint(b)));
    return v;
}
__device__ __forceinline__ ull PKU(unsigned a, unsigned b) {
    ull v; asm("mov.b64 %0, {%1, %2};" : "=l"(v) : "r"(a), "r"(b));
    return v;
}
__device__ __forceinline__ float LO(ull v) { return __uint_as_float((unsigned)v); }
__device__ __forceinline__ float HI(ull v) { return __uint_as_float((unsigned)(v >> 32)); }
__device__ __forceinline__ ull FMA2(ull a, ull b, ull c) {
    ull d; asm("fma.rn.f32x2 %0, %1, %2, %3;" : "=l"(d) : "l"(a), "l"(b), "l"(c));
    return d;
}
__device__ __forceinline__ ull MUL2(ull a, ull b) {
    ull d; asm("mul.rn.f32x2 %0, %1, %2;" : "=l"(d) : "l"(a), "l"(b));
    return d;
}
__device__ __forceinline__ ull ADD2(ull a, ull b) {
    ull d; asm("add.rn.f32x2 %0, %1, %2;" : "=l"(d) : "l"(a), "l"(b));
    return d;
}
__device__ __forceinline__ ull SPL(float a) { return PKF(a, a); }

__device__ __forceinline__ void cp16(uint32_t dst, const void* src) {
    asm volatile("cp.async.cg.shared.global [%0], [%1], 16;" :: "r"(dst), "l"(src));
}

__global__ void __launch_bounds__(TPB, 1) vmc_kernel(
    const float* __restrict__ theta,
    const float* __restrict__ r0,
    const float* __restrict__ sdevp,
    const float* __restrict__ noise,
    const float* __restrict__ unif,
    float* __restrict__ out, int out_size)
{
    extern __shared__ ull ring[];
    float* shred = (float*)ring;             // aliased reduction scratch

    const int tid = threadIdx.x;
    const int blk = blockIdx.x;
    const int w   = blk * PPB + tid;         // walker-pair index

    const float th0 = theta[0];
    const float th1 = theta[1];
    const float th2 = theta[2];
    const float sdev = sdevp[0];

    const float kk = __fmul_rn(-2.0f, th1);   // reference rounding (validated)
    const float gf = 2.0f * th1;

    const ull sd2  = SPL(sdev);
    const ull kk2  = SPL(kk);
    const ull mkk2 = SPL(-kk);

    // cheap comparison-grade ln: m in [2/3,4/3), f=m-1; ln(1+f) ~= f*P(f),
    // P = deg-5 Taylor (abs err <= 6e-5; flips ~1e3 of 33.5M -> safe)
    const ull cm1 = SPL(-1.0f);
    const ull cP5 = SPL(-0.16666667f), cP4 = SPL(0.2f);
    const ull cP3 = SPL(-0.25f),       cP2 = SPL(0.33333334f);
    const ull cP1 = SPL(-0.5f),        cP0 = SPL(1.0f);
    const ull cE  = SPL(8.2629582e-8f);      // 2^-23 * ln 2

    // Energy poly coefficients (fp64 fold once); applied only in epilogue
    const double dth0 = (double)th0, dth1 = (double)th1;
    const double dg = 2.0 * dth1, g2d = dg * dg;
    const double dC1 = -2.0 * exp(-dth1) * cos(dth0);
    const double dC2 =  2.0 * exp(-dth1) * sin(dth0);
    const float A0f = (float)dC1;
    const float A1f = (float)(dC1 * g2d / 2.0);
    const float A2f = (float)(dC1 * g2d / 2.0 * g2d / 12.0);
    const float A3f = (float)(dC1 * g2d / 2.0 * g2d / 12.0 * g2d / 30.0);
    const float B0f = (float)(dC2 * dg);
    const float B1f = (float)(dC2 * dg * g2d / 6.0);
    const float B2f = (float)(dC2 * dg * g2d / 6.0 * g2d / 20.0);

    // ---- state: one packed pair per thread ----
    const float2 rr = ((const float2*)r0)[w];
    ull xs  = PKF(__fsub_rn(rr.x, th2), __fsub_rn(rr.y, th2));
    ull xs2 = MUL2(xs, xs);
    ull nkx = MUL2(mkk2, xs2);

    // ---- cp.async geometry (validated R5/R9) ----
    const uint32_t base = (uint32_t)__cvta_generic_to_shared(ring);
    const int c16  = tid & 127;
    const int rsel = tid >> 7;
    const size_t sliceOff = (size_t)blk * 2048 + (size_t)c16 * 16;
    const char* gN = (const char*)noise + sliceOff;
    const char* gU = (const char*)unif  + sliceOff;

#define ISSUE_CHUNK(s0, stg) do {                                            \
        const char* _n = gN + (size_t)(s0) * ROWB;                           \
        const char* _u = gU + (size_t)(s0) * ROWB;                           \
        uint32_t _sb = base + (uint32_t)(stg) * (STG * 8);                   \
        _Pragma("unroll")                                                    \
        for (int _k = 0; _k < 4; _k++) {                                     \
            int _row = _k * 2 + rsel;                                        \
            uint32_t _d = (uint32_t)(_row * 2048 + c16 * 16);                \
            cp16(_sb + _d,            _n + (size_t)_row * ROWB);             \
            cp16(_sb + UOFF * 8 + _d, _u + (size_t)_row * ROWB);             \
        }                                                                    \
        asm volatile("cp.async.commit_group;" ::: "memory");                 \
    } while (0)

    // packed cheap natural log (off-chain): 8 fma-pipe ops
#define NLOG(u, lgu) do {                                                    \
        unsigned iu0 = (unsigned)(u);                                        \
        unsigned iu1 = (unsigned)((u) >> 32);                                \
        int e0 = (int)((iu0 - 0x3f2aaaabu) & 0xff800000u);                   \
        int e1 = (int)((iu1 - 0x3f2aaaabu) & 0xff800000u);                   \
        float mm0 = __int_as_float((int)iu0 - e0);                           \
        float mm1 = __int_as_float((int)iu1 - e1);                           \
        ull f_ = ADD2(PKF(mm0, mm1), cm1);                                   \
        ull p_ = FMA2(cP5, f_, cP4);                                         \
        p_ = FMA2(p_, f_, cP3);                                              \
        p_ = FMA2(p_, f_, cP2);                                              \
        p_ = FMA2(p_, f_, cP1);                                              \
        p_ = FMA2(p_, f_, cP0);                                              \
        ull ln_ = MUL2(f_, p_);                                              \
        (lgu) = FMA2(PKF((float)e0, (float)e1), cE, ln_);                    \
    } while (0)

    // short recurrence; proposal fused: xp = sdev*n + xs (1 FMA2)
#define REC(nn, lg) do {                                                     \
        ull xp  = FMA2(sd2, (nn), xs);                                       \
        ull xp2 = MUL2(xp, xp);                                              \
        ull lr  = FMA2(kk2, xp2, nkx);                                       \
        bool aLo = (LO(lg) < LO(lr));                                        \
        bool aHi = (HI(lg) < HI(lr));                                        \
        unsigned xs_lo = aLo ? (unsigned)xp         : (unsigned)xs;          \
        unsigned xs_hi = aHi ? (unsigned)(xp  >> 32) : (unsigned)(xs  >> 32); \
        unsigned x2_lo = aLo ? (unsigned)xp2        : (unsigned)xs2;         \
        unsigned x2_hi = aHi ? (unsigned)(xp2 >> 32) : (unsigned)(xs2 >> 32); \
        xs  = PKU(xs_lo, xs_hi);                                             \
        xs2 = PKU(x2_lo, x2_hi);                                             \
        nkx = MUL2(mkk2, xs2);                                               \
    } while (0)

    // moment accumulation: M1=Sxs M2=St M3=Sxs3 M4=St2 M5=Sxs5 M6=St3
#define MEAS() do {                                                          \
        ull t   = xs2;                                                       \
        ull x3  = MUL2(xs, t);                                               \
        ull t2  = MUL2(t, t);                                                \
        M1 = ADD2(M1, xs);                                                   \
        M2 = ADD2(M2, t);                                                    \
        M3 = ADD2(M3, x3);                                                   \
        M4 = ADD2(M4, t2);                                                   \
        M5 = FMA2(x3, t, M5);                                                \
        M6 = FMA2(t2, t, M6);                                                \
    } while (0)

    ull M1 = 0, M2 = 0, M3 = 0, M4 = 0, M5 = 0, M6 = 0;

    ISSUE_CHUNK(0 * CH, 0);
    ISSUE_CHUNK(1 * CH, 1);
    ISSUE_CHUNK(2 * CH, 2);

    for (int c = 0; c < NCH; c++) {
        asm volatile("cp.async.wait_group 2;" ::: "memory");
        __syncthreads();

        if (c + 3 < NCH) {
            ISSUE_CHUNK((c + 3) * CH, (c + 3) & 3);
        } else {
            asm volatile("cp.async.commit_group;" ::: "memory");
        }

        const ull* st = ring + (size_t)(c & 3) * STG;
        const bool meas = (c >= WARM_CH);

#pragma unroll
        for (int h = 0; h < CH / HB; h++) {
            ull nn[HB], lg[HB];
#pragma unroll
            for (int j = 0; j < HB; j++) {
                const int row = h * HB + j;
                nn[j] = st[row * PPB + tid];
                ull u = st[UOFF + row * PPB + tid];
                NLOG(u, lg[j]);
            }
            if (!meas) {
#pragma unroll
                for (int j = 0; j < HB; j++) { REC(nn[j], lg[j]); }
            } else {
#pragma unroll
                for (int j = 0; j < HB; j++) { REC(nn[j], lg[j]); MEAS(); }
            }
        }
    }

    // ------- block reduction: R9-validated shape, 8 slots (2 zero pads) -------
    float v0 = LO(M1) + HI(M1), v1 = LO(M2) + HI(M2);
    float v2 = LO(M3) + HI(M3), v3 = LO(M4) + HI(M4);
    float v4 = LO(M5) + HI(M5), v5 = LO(M6) + HI(M6);
    float v6 = 0.0f,            v7 = 0.0f;

    const unsigned m = 0xffffffffu;
#pragma unroll
    for (int o = 16; o; o >>= 1) {
        v0 += __shfl_xor_sync(m, v0, o);
        v1 += __shfl_xor_sync(m, v1, o);
        v2 += __shfl_xor_sync(m, v2, o);
        v3 += __shfl_xor_sync(m, v3, o);
        v4 += __shfl_xor_sync(m, v4, o);
        v5 += __shfl_xor_sync(m, v5, o);
    }

    float* sh   = shred;            // [8][8]
    float* s8   = shred + 64;       // [8]
    int*  sLast = (int*)(shred + 72);

    __syncthreads();                // ring reads done before aliasing
    const int lane = tid & 31;
    const int wp   = tid >> 5;      // 8 warps
    if (lane == 0) {
        sh[0 * 8 + wp] = v0; sh[1 * 8 + wp] = v1;
        sh[2 * 8 + wp] = v2; sh[3 * 8 + wp] = v3;
        sh[4 * 8 + wp] = v4; sh[5 * 8 + wp] = v5;
        sh[6 * 8 + wp] = v6; sh[7 * 8 + wp] = v7;
    }
    __syncthreads();
    if (tid < 64) {                 // 2 FULL warps participate in shuffles
        const int q  = tid >> 3;
        const int wj = tid & 7;
        float v = sh[q * 8 + wj];
        v += __shfl_down_sync(m, v, 4, 8);
        v += __shfl_down_sync(m, v, 2, 8);
        v += __shfl_down_sync(m, v, 1, 8);
        if (wj == 0) g_part[q][blk] = v;
    }
    __threadfence();
    __syncthreads();
    if (tid == 0) {
        unsigned old = atomicAdd(&g_ctr, 1u);
        *sLast = ((old % NBLK) == (NBLK - 1)) ? 1 : 0;
    }
    __syncthreads();

    // ---------------- last block: final reduce + epilogue ----------------
    if (*sLast) {
        if (tid < 128) {            // 4 FULL warps participate in shuffles
            const int q = tid >> 4;   // 8 quantities x 16 lanes
            const int l = tid & 15;
            float v = 0.f;
#pragma unroll
            for (int i = l; i < NBLK; i += 16) v += __ldcg(&g_part[q][i]);
#pragma unroll
            for (int o = 8; o; o >>= 1) v += __shfl_down_sync(m, v, o, 16);
            if (l == 0) s8[q] = v;
        }
        __syncthreads();

        if (tid == 0) {
            const float inv = 1.0f / ((float)NW * (float)NSTEPS);
            const float m1 = s8[0] * inv;   // mean xs
            const float m2 = s8[1] * inv;   // mean xs^2
            const float m3 = s8[2] * inv;   // mean xs^3
            const float m4 = s8[3] * inv;   // mean xs^4
            const float m5 = s8[4] * inv;   // mean xs^5
            const float m6 = s8[5] * inv;   // mean xs^6

            // linear recombination (er = A0+A1 t+A2 t^2+A3 t^3, ei = xs*(B0+B1 t+B2 t^2))
            const float Ser   = A0f + A1f * m2 + A2f * m4 + A3f * m6;
            const float Sei   = B0f * m1 + B1f * m3 + B2f * m5;
            const float Sxs   = m1;
            const float Sx2   = m2;
            const float Sxer  = A0f * m1 + A1f * m3 + A2f * m5;
            const float Sxei  = B0f * m2 + B1f * m4 + B2f * m6;
            const float Sx2er = A0f * m2 + A1f * m4 + A2f * m6;
            const float Sx2ei = B0f * m3 + B1f * m5;

            if (out_size == 14) {
                const float Sr   = Sxs + th2;
                const float Srer = Sxer + th2 * Ser;
                const float Srei = Sxei + th2 * Sei;
                float2* o2 = (float2*)out;
                o2[0] = make_float2(Ser, Sei);
                o2[1] = make_float2(0.0f, Sr);
                o2[2] = make_float2(Sx2, 0.0f);
                o2[3] = make_float2(gf * Sxs, 0.0f);
                o2[4] = make_float2(Srei, -Srer);
                o2[5] = make_float2(Sx2er, Sx2ei);
                o2[6] = make_float2(gf * Sxer, gf * Sxei);
            } else {
                out[0] = Ser;                  // Es.re
                out[1] = 0.0f;                 // Ds0.re
                out[2] = Sx2;                  // Ds1.re
                out[3] = gf * Sxs;             // Ds2.re
                out[4] = Sxei + th2 * Sei;     // EDs0.re
                out[5] = Sx2er;                // EDs1.re
                out[6] = gf * Sxer;            // EDs2.re
            }
        }
    }
}

extern "C" void kernel_launch(void* const* d_in, const int* in_sizes, int n_in,
                              void* d_out, int out_size)
{
    const float* theta = (const float*)d_in[0];
    const float* r0    = (const float*)d_in[1];
    const float* sdev  = (const float*)d_in[2];
    const float* noise = (const float*)d_in[3];
    const float* unif  = (const float*)d_in[4];

    cudaFuncSetAttribute(vmc_kernel, cudaFuncAttributeMaxDynamicSharedMemorySize,
                         SMEM_BYTES);

    vmc_kernel<<<NBLK, TPB, SMEM_BYTES>>>(theta, r0, sdev, noise, unif,
                                          (float*)d_out, out_size);
}

// round 12
// speedup vs baseline: 1.3941x; 1.1121x over previous
#include <cuda_runtime.h>
#include <math.h>
#include <stdint.h>

// Problem constants (fixed by the reference)
#define NW      65536
#define TPB     256
#define PPB     256                // walker pairs per block (1 packed pair/thread)
#define NBLK    128                // 32768 pairs / 256; divides 2^32
#define TOTALS  512
#define WARM    128
#define NSTEPS  384
#define CH      16                 // steps per chunk
#define HB      4                  // steps per precompute half-block
#define NCH     (TOTALS / CH)      // 32
#define WARM_CH (WARM / CH)        // 8
#define ROWB    ((size_t)NW * 4)   // gmem bytes per step-row
// smem ring (ull units): stage = [N: CH*PPB][U: CH*PPB]
#define UOFF    (CH * PPB)         // 4096 ull
#define STG     (2 * CH * PPB)     // 8192 ull = 64 KB
#define SMEM_BYTES (3 * STG * 8)   // 192 KB

typedef unsigned long long ull;

// 8 slots (4 moments + 4 zero pads) keeps the validated reduction shape
__device__ float        g_part[8][NBLK];
__device__ unsigned int g_ctr = 0;

// ---------- f32x2 packed helpers ----------
__device__ __forceinline__ ull PKF(float a, float b) {
    ull v; asm("mov.b64 %0, {%1, %2};" : "=l"(v)
               : "r"(__float_as_uint(a)), "r"(__float_as_uint(b)));
    return v;
}
__device__ __forceinline__ ull PKU(unsigned a, unsigned b) {
    ull v; asm("mov.b64 %0, {%1, %2};" : "=l"(v) : "r"(a), "r"(b));
    return v;
}
__device__ __forceinline__ float LO(ull v) { return __uint_as_float((unsigned)v); }
__device__ __forceinline__ float HI(ull v) { return __uint_as_float((unsigned)(v >> 32)); }
__device__ __forceinline__ ull FMA2(ull a, ull b, ull c) {
    ull d; asm("fma.rn.f32x2 %0, %1, %2, %3;" : "=l"(d) : "l"(a), "l"(b), "l"(c));
    return d;
}
__device__ __forceinline__ ull MUL2(ull a, ull b) {
    ull d; asm("mul.rn.f32x2 %0, %1, %2;" : "=l"(d) : "l"(a), "l"(b));
    return d;
}
__device__ __forceinline__ ull ADD2(ull a, ull b) {
    ull d; asm("add.rn.f32x2 %0, %1, %2;" : "=l"(d) : "l"(a), "l"(b));
    return d;
}
__device__ __forceinline__ ull SPL(float a) { return PKF(a, a); }

__device__ __forceinline__ void cp16(uint32_t dst, const void* src) {
    asm volatile("cp.async.cg.shared.global [%0], [%1], 16;" :: "r"(dst), "l"(src));
}

__global__ void __launch_bounds__(TPB, 1) vmc_kernel(
    const float* __restrict__ theta,
    const float* __restrict__ r0,
    const float* __restrict__ sdevp,
    const float* __restrict__ noise,
    const float* __restrict__ unif,
    float* __restrict__ out, int out_size)
{
    extern __shared__ ull ring[];
    float* shred = (float*)ring;             // aliased reduction scratch

    const int tid = threadIdx.x;
    const int blk = blockIdx.x;
    const int w   = blk * PPB + tid;         // walker-pair index

    const float th0 = theta[0];
    const float th1 = theta[1];
    const float th2 = theta[2];
    const float sdev = sdevp[0];

    const float kk = __fmul_rn(-2.0f, th1);   // reference rounding (validated)
    const float gf = 2.0f * th1;

    const ull sd2  = SPL(sdev);
    const ull kk2  = SPL(kk);
    const ull mkk2 = SPL(-kk);

    // cheap comparison-grade ln (validated R11): m in [2/3,4/3), f=m-1
    const ull cm1 = SPL(-1.0f);
    const ull cP5 = SPL(-0.16666667f), cP4 = SPL(0.2f);
    const ull cP3 = SPL(-0.25f),       cP2 = SPL(0.33333334f);
    const ull cP1 = SPL(-0.5f),        cP0 = SPL(1.0f);
    const ull cE  = SPL(8.2629582e-8f);      // 2^-23 * ln 2

    // Energy poly coefficients (fp64 fold once); applied only in epilogue
    const double dth0 = (double)th0, dth1 = (double)th1;
    const double dg = 2.0 * dth1, g2d = dg * dg;
    const double dC1 = -2.0 * exp(-dth1) * cos(dth0);
    const double dC2 =  2.0 * exp(-dth1) * sin(dth0);
    const float A0f = (float)dC1;
    const float A1f = (float)(dC1 * g2d / 2.0);
    const float A2f = (float)(dC1 * g2d / 2.0 * g2d / 12.0);
    const float B0f = (float)(dC2 * dg);
    const float B1f = (float)(dC2 * dg * g2d / 6.0);

    // ---- state: one packed pair per thread ----
    const float2 rr = ((const float2*)r0)[w];
    ull xs  = PKF(__fsub_rn(rr.x, th2), __fsub_rn(rr.y, th2));
    ull xs2 = MUL2(xs, xs);
    ull nkx = MUL2(mkk2, xs2);

    // ---- cp.async geometry ----
    const uint32_t base = (uint32_t)__cvta_generic_to_shared(ring);
    const int c16  = tid & 127;
    const int rsel = tid >> 7;
    const size_t sliceOff = (size_t)blk * 2048 + (size_t)c16 * 16;
    const char* gN = (const char*)noise + sliceOff;
    const char* gU = (const char*)unif  + sliceOff;

    // chunk = 16 rows; each thread: 8 rows x (N,U) granules of 16 B
#define ISSUE_CHUNK(s0, stg) do {                                            \
        const char* _n = gN + (size_t)(s0) * ROWB;                           \
        const char* _u = gU + (size_t)(s0) * ROWB;                           \
        uint32_t _sb = base + (uint32_t)(stg) * (STG * 8);                   \
        _Pragma("unroll")                                                    \
        for (int _k = 0; _k < 8; _k++) {                                     \
            int _row = _k * 2 + rsel;                                        \
            uint32_t _d = (uint32_t)(_row * 2048 + c16 * 16);                \
            cp16(_sb + _d,            _n + (size_t)_row * ROWB);             \
            cp16(_sb + UOFF * 8 + _d, _u + (size_t)_row * ROWB);             \
        }                                                                    \
        asm volatile("cp.async.commit_group;" ::: "memory");                 \
    } while (0)

    // packed cheap natural log (off-chain): 8 fma-pipe ops
#define NLOG(u, lgu) do {                                                    \
        unsigned iu0 = (unsigned)(u);                                        \
        unsigned iu1 = (unsigned)((u) >> 32);                                \
        int e0 = (int)((iu0 - 0x3f2aaaabu) & 0xff800000u);                   \
        int e1 = (int)((iu1 - 0x3f2aaaabu) & 0xff800000u);                   \
        float mm0 = __int_as_float((int)iu0 - e0);                           \
        float mm1 = __int_as_float((int)iu1 - e1);                           \
        ull f_ = ADD2(PKF(mm0, mm1), cm1);                                   \
        ull p_ = FMA2(cP5, f_, cP4);                                         \
        p_ = FMA2(p_, f_, cP3);                                              \
        p_ = FMA2(p_, f_, cP2);                                              \
        p_ = FMA2(p_, f_, cP1);                                              \
        p_ = FMA2(p_, f_, cP0);                                              \
        ull ln_ = MUL2(f_, p_);                                              \
        (lgu) = FMA2(PKF((float)e0, (float)e1), cE, ln_);                    \
    } while (0)

    // short recurrence; proposal fused: xp = sdev*n + xs (1 FMA2)
#define REC(nn, lg) do {                                                     \
        ull xp  = FMA2(sd2, (nn), xs);                                       \
        ull xp2 = MUL2(xp, xp);                                              \
        ull lr  = FMA2(kk2, xp2, nkx);                                       \
        bool aLo = (LO(lg) < LO(lr));                                        \
        bool aHi = (HI(lg) < HI(lr));                                        \
        unsigned xs_lo = aLo ? (unsigned)xp         : (unsigned)xs;          \
        unsigned xs_hi = aHi ? (unsigned)(xp  >> 32) : (unsigned)(xs  >> 32); \
        unsigned x2_lo = aLo ? (unsigned)xp2        : (unsigned)xs2;         \
        unsigned x2_hi = aHi ? (unsigned)(xp2 >> 32) : (unsigned)(xs2 >> 32); \
        xs  = PKU(xs_lo, xs_hi);                                             \
        xs2 = PKU(x2_lo, x2_hi);                                             \
        nkx = MUL2(mkk2, xs2);                                               \
    } while (0)

    // moment accumulation: M1=Sxs M2=St M3=Sxs3 M4=St2 (M5/M6 dropped; err<=1e-4)
#define MEAS() do {                                                          \
        ull t   = xs2;                                                       \
        ull x3  = MUL2(xs, t);                                               \
        ull t2  = MUL2(t, t);                                                \
        M1 = ADD2(M1, xs);                                                   \
        M2 = ADD2(M2, t);                                                    \
        M3 = ADD2(M3, x3);                                                   \
        M4 = ADD2(M4, t2);                                                   \
    } while (0)

    ull M1 = 0, M2 = 0, M3 = 0, M4 = 0;

    // prologue: 2 chunks in flight (3-stage ring)
    ISSUE_CHUNK(0 * CH, 0);
    ISSUE_CHUNK(1 * CH, 1);

    int cur = 0;                    // slot of chunk c
    for (int c = 0; c < NCH; c++) {
        asm volatile("cp.async.wait_group 1;" ::: "memory");  // chunk c complete
        __syncthreads();            // visibility + all threads done with slot iss

        const int iss = (cur == 0) ? 2 : cur - 1;   // (c+2) % 3
        if (c + 2 < NCH) {
            ISSUE_CHUNK((c + 2) * CH, iss);
        } else {
            asm volatile("cp.async.commit_group;" ::: "memory");
        }

        const ull* st = ring + (size_t)cur * STG;
        const bool meas = (c >= WARM_CH);

#pragma unroll
        for (int h = 0; h < CH / HB; h++) {
            ull nn[HB], lg[HB];
#pragma unroll
            for (int j = 0; j < HB; j++) {
                const int row = h * HB + j;
                nn[j] = st[row * PPB + tid];
                ull u = st[UOFF + row * PPB + tid];
                NLOG(u, lg[j]);
            }
            if (!meas) {
#pragma unroll
                for (int j = 0; j < HB; j++) { REC(nn[j], lg[j]); }
            } else {
#pragma unroll
                for (int j = 0; j < HB; j++) { REC(nn[j], lg[j]); MEAS(); }
            }
        }
        cur = (cur == 2) ? 0 : cur + 1;
    }

    // ------- block reduction: validated shape, 8 slots (4 zero pads) -------
    float v0 = LO(M1) + HI(M1), v1 = LO(M2) + HI(M2);
    float v2 = LO(M3) + HI(M3), v3 = LO(M4) + HI(M4);
    float v4 = 0.0f, v5 = 0.0f, v6 = 0.0f, v7 = 0.0f;

    const unsigned m = 0xffffffffu;
#pragma unroll
    for (int o = 16; o; o >>= 1) {
        v0 += __shfl_xor_sync(m, v0, o);
        v1 += __shfl_xor_sync(m, v1, o);
        v2 += __shfl_xor_sync(m, v2, o);
        v3 += __shfl_xor_sync(m, v3, o);
    }

    float* sh   = shred;            // [8][8]
    float* s8   = shred + 64;       // [8]
    int*  sLast = (int*)(shred + 72);

    __syncthreads();                // ring reads done before aliasing
    const int lane = tid & 31;
    const int wp   = tid >> 5;      // 8 warps
    if (lane == 0) {
        sh[0 * 8 + wp] = v0; sh[1 * 8 + wp] = v1;
        sh[2 * 8 + wp] = v2; sh[3 * 8 + wp] = v3;
        sh[4 * 8 + wp] = v4; sh[5 * 8 + wp] = v5;
        sh[6 * 8 + wp] = v6; sh[7 * 8 + wp] = v7;
    }
    __syncthreads();
    if (tid < 64) {                 // 2 FULL warps in shuffles
        const int q  = tid >> 3;
        const int wj = tid & 7;
        float v = sh[q * 8 + wj];
        v += __shfl_down_sync(m, v, 4, 8);
        v += __shfl_down_sync(m, v, 2, 8);
        v += __shfl_down_sync(m, v, 1, 8);
        if (wj == 0) g_part[q][blk] = v;
    }
    __threadfence();
    __syncthreads();
    if (tid == 0) {
        unsigned old = atomicAdd(&g_ctr, 1u);
        *sLast = ((old % NBLK) == (NBLK - 1)) ? 1 : 0;
    }
    __syncthreads();

    // ---------------- last block: final reduce + epilogue ----------------
    if (*sLast) {
        if (tid < 128) {            // 4 FULL warps in shuffles
            const int q = tid >> 4;   // 8 quantities x 16 lanes
            const int l = tid & 15;
            float v = 0.f;
#pragma unroll
            for (int i = l; i < NBLK; i += 16) v += __ldcg(&g_part[q][i]);
#pragma unroll
            for (int o = 8; o; o >>= 1) v += __shfl_down_sync(m, v, o, 16);
            if (l == 0) s8[q] = v;
        }
        __syncthreads();

        if (tid == 0) {
            const float inv = 1.0f / ((float)NW * (float)NSTEPS);
            const float m1 = s8[0] * inv;   // mean xs
            const float m2 = s8[1] * inv;   // mean xs^2
            const float m3 = s8[2] * inv;   // mean xs^3
            const float m4 = s8[3] * inv;   // mean xs^4

            // linear recombination (er = A0+A1 t+A2 t^2, ei = xs*(B0+B1 t))
            const float Ser   = A0f + A1f * m2 + A2f * m4;
            const float Sei   = B0f * m1 + B1f * m3;
            const float Sxs   = m1;
            const float Sx2   = m2;
            const float Sxer  = A0f * m1 + A1f * m3;
            const float Sxei  = B0f * m2 + B1f * m4;
            const float Sx2er = A0f * m2 + A1f * m4;
            const float Sx2ei = B0f * m3;

            if (out_size == 14) {
                const float Sr   = Sxs + th2;
                const float Srer = Sxer + th2 * Ser;
                const float Srei = Sxei + th2 * Sei;
                float2* o2 = (float2*)out;
                o2[0] = make_float2(Ser, Sei);
                o2[1] = make_float2(0.0f, Sr);
                o2[2] = make_float2(Sx2, 0.0f);
                o2[3] = make_float2(gf * Sxs, 0.0f);
                o2[4] = make_float2(Srei, -Srer);
                o2[5] = make_float2(Sx2er, Sx2ei);
                o2[6] = make_float2(gf * Sxer, gf * Sxei);
            } else {
                out[0] = Ser;                  // Es.re
                out[1] = 0.0f;                 // Ds0.re
                out[2] = Sx2;                  // Ds1.re
                out[3] = gf * Sxs;             // Ds2.re
                out[4] = Sxei + th2 * Sei;     // EDs0.re
                out[5] = Sx2er;                // EDs1.re
                out[6] = gf * Sxer;            // EDs2.re
            }
        }
    }
}

extern "C" void kernel_launch(void* const* d_in, const int* in_sizes, int n_in,
                              void* d_out, int out_size)
{
    const float* theta = (const float*)d_in[0];
    const float* r0    = (const float*)d_in[1];
    const float* sdev  = (const float*)d_in[2];
    const float* noise = (const float*)d_in[3];
    const float* unif  = (const float*)d_in[4];

    cudaFuncSetAttribute(vmc_kernel, cudaFuncAttributeMaxDynamicSharedMemorySize,
                         SMEM_BYTES);

    vmc_kernel<<<NBLK, TPB, SMEM_BYTES>>>(theta, r0, sdev, noise, unif,
                                          (float*)d_out, out_size);
}